// round 8
// baseline (speedup 1.0000x reference)
#include <cuda_runtime.h>
#include <cstdint>

typedef unsigned long long ull;

#define B_TILE   16
#define NTHREADS 512
#define T        64
#define D        128
#define CTILE    16          // columns per weight tile (floats)
#define NTILES   8           // 128 / 16
#define RSTRIDE  20          // padded tile row stride in floats (5 float4, conflict-free)
#define NROWS    576         // wk(128)+wq(128)+wv(128)+wo(128)+V(64)
#define TILE_F   (NROWS * RSTRIDE)   // 11520 floats per buffer

// dynamic smem layout (float offsets)
#define OFF_WS    0                       // 2*11520 = 23040 (reused as Y after main loop)
#define OFF_Y     0                       // [b][row<512] : 16*512 = 8192 floats
#define OFF_STATE (2 * TILE_F)            // 23040 : 2048
#define OFF_X     (OFF_STATE + B_TILE*D)  // 25088 : 1024
#define OFF_V     (OFF_X + B_TILE*T)      // 26112 : 1024
#define OFF_S     (OFF_V + B_TILE*T)      // 27136
#define OFF_D     (OFF_S + B_TILE)
#define OFF_MN    (OFF_D + B_TILE)
#define OFF_MX    (OFF_MN + B_TILE)
#define SMEM_F    (OFF_MX + B_TILE)       // 27200 floats = 108800 B

__device__ __forceinline__ ull ffma2(ull a, ull b, ull c) {
    ull r;
    asm("fma.rn.f32x2 %0, %1, %2, %3;" : "=l"(r) : "l"(a), "l"(b), "l"(c));
    return r;
}
__device__ __forceinline__ ull add2(ull a, ull b) {
    ull r;
    asm("add.rn.f32x2 %0, %1, %2;" : "=l"(r) : "l"(a), "l"(b));
    return r;
}
__device__ __forceinline__ float sum2(ull a) {
    float lo, hi;
    asm("mov.b64 {%0, %1}, %2;" : "=f"(lo), "=f"(hi) : "l"(a));
    return lo + hi;
}
__device__ __forceinline__ void unpack2(ull a, float& lo, float& hi) {
    asm("mov.b64 {%0, %1}, %2;" : "=f"(lo), "=f"(hi) : "l"(a));
}
__device__ __forceinline__ ull pack2f(float lo, float hi) {
    ull r;
    asm("mov.b64 %0, {%1, %2};" : "=l"(r) : "f"(lo), "f"(hi));
    return r;
}
__device__ __forceinline__ float ex2f(float x) {
    float r; asm("ex2.approx.ftz.f32 %0, %1;" : "=f"(r) : "f"(x)); return r;
}
__device__ __forceinline__ void cp16(unsigned int dst, const void* src) {
    asm volatile("cp.async.ca.shared.global [%0], [%1], 16;" :: "r"(dst), "l"(src));
}
__device__ __forceinline__ void cp_commit() {
    asm volatile("cp.async.commit_group;" ::: "memory");
}
template<int N> __device__ __forceinline__ void cp_wait() {
    asm volatile("cp.async.wait_group %0;" :: "n"(N) : "memory");
}

__global__ void __launch_bounds__(NTHREADS, 2)
fused_hyper_attn(const float* __restrict__ x, const float* __restrict__ state,
                 const float* __restrict__ wk_w, const float* __restrict__ wk_b,
                 const float* __restrict__ wq_w, const float* __restrict__ wq_b,
                 const float* __restrict__ wv_w, const float* __restrict__ wv_b,
                 const float* __restrict__ wo_w, const float* __restrict__ wo_b,
                 const float* __restrict__ V_w,  const float* __restrict__ V_b,
                 float* __restrict__ out)
{
    extern __shared__ __align__(16) float sm[];
    const int t  = threadIdx.x;           // 0..511
    const int b0 = blockIdx.x * B_TILE;
    const unsigned int sm_u32 = (unsigned int)__cvta_generic_to_shared(sm);

    // ---- stage weight tiles (cp.async, double buffered); 2304 16B-chunks/tile ----
    #define STAGE(TI)                                                          \
    do {                                                                       \
        const int c0_ = (TI) * CTILE;                                          \
        const unsigned int wb_ = sm_u32 + (OFF_WS + ((TI) & 1) * TILE_F) * 4;  \
        _Pragma("unroll")                                                      \
        for (int i_ = 0; i_ < 5; i_++) {                                       \
            int q_ = t + i_ * NTHREADS;                                        \
            if (i_ == 4 && q_ >= 2304) break;                                  \
            int row_ = q_ >> 2, cq_ = q_ & 3;                                  \
            const float* src_;                                                 \
            if      (row_ < 128) src_ = wk_w + (size_t)row_ * D;               \
            else if (row_ < 256) src_ = wq_w + (size_t)(row_ - 128) * D;       \
            else if (row_ < 384) src_ = wv_w + (size_t)(row_ - 256) * D;       \
            else if (row_ < 512) src_ = wo_w + (size_t)(row_ - 384) * D;       \
            else                 src_ = V_w  + (size_t)(row_ - 512) * D;       \
            cp16(wb_ + (unsigned int)(row_ * RSTRIDE + cq_ * 4) * 4,           \
                 src_ + c0_ + cq_ * 4);                                        \
        }                                                                      \
        cp_commit();                                                           \
    } while (0)

    STAGE(0);
    STAGE(1);

    // ---- stage state (16x128) and x (16x64) ----
    ((float4*)(sm + OFF_STATE))[t] = ((const float4*)(state + (size_t)b0 * D))[t];
    if (t < 256)
        ((float4*)(sm + OFF_X))[t] = ((const float4*)(x + (size_t)b0 * T))[t];
    __syncthreads();   // state/x visible

    // ---- per-batch min/max of x (16 threads, overlapped with tile waits) ----
    if (t < B_TILE) {
        const float* xr = sm + OFF_X + t * T;
        float mn = xr[0], mx = mn;
        #pragma unroll
        for (int k = 1; k < T; k++) {
            float v = xr[k];
            mn = fminf(mn, v); mx = fmaxf(mx, v);
        }
        sm[OFF_MN + t] = mn; sm[OFF_MX + t] = mx;
    }

    // ---- ownership: thread t owns hypernet row t (all 16 batches);
    //      warp w owns batch w for V: lanes are V rows (l, l+32) ----
    const int lane = t & 31;
    const int bV   = t >> 5;              // 0..15, uniform per warp
    const int rV0  = lane;                // V_w rows
    const int rV1  = lane + 32;

    ull accM[B_TILE], accV0 = 0ull, accV1 = 0ull;
    #pragma unroll
    for (int b = 0; b < B_TILE; b++) accM[b] = 0ull;

    const ulonglong2* st = (const ulonglong2*)(sm + OFF_STATE);  // [16][32] 16B units

    // ---- pipelined main loop over 8 column tiles ----
    for (int ti = 0; ti < NTILES; ti++) {
        if (ti < NTILES - 1) cp_wait<1>(); else cp_wait<0>();
        __syncthreads();                       // tile ti visible to all

        const ulonglong2* wt = (const ulonglong2*)(sm + OFF_WS + (ti & 1) * TILE_F);
        const int jb = ti * 4;                 // ulonglong2-column base in state row
        #pragma unroll
        for (int j = 0; j < 4; j++) {
            ulonglong2 wu = wt[t * 5 + j];               // own row's 4 cols
            ulonglong2 v0 = wt[(512 + rV0) * 5 + j];
            ulonglong2 v1 = wt[(512 + rV1) * 5 + j];
            ulonglong2 sv = st[bV * 32 + jb + j];        // broadcast
            accV0 = ffma2(sv.x, v0.x, accV0);
            accV0 = ffma2(sv.y, v0.y, accV0);
            accV1 = ffma2(sv.x, v1.x, accV1);
            accV1 = ffma2(sv.y, v1.y, accV1);
            #pragma unroll
            for (int b = 0; b < B_TILE; b++) {
                ulonglong2 s = st[b * 32 + jb + j];      // broadcast
                accM[b] = ffma2(s.x, wu.x, accM[b]);
                accM[b] = ffma2(s.y, wu.y, accM[b]);
            }
        }

        __syncthreads();                       // all done reading buf[ti&1]
        if (ti + 2 < NTILES) STAGE(ti + 2);
    }

    // ---- finalize: |y + bias| to Y[b][row] (overlaid on weight buffers) ----
    {
        float bias;
        if      (t < 128) bias = wk_b[t];
        else if (t < 256) bias = wq_b[t - 128];
        else if (t < 384) bias = wv_b[t - 256];
        else              bias = wo_b[t - 384];
        #pragma unroll
        for (int b = 0; b < B_TILE; b++)
            sm[OFF_Y + b * 512 + t] = fabsf(sum2(accM[b]) + bias);
        // v[bV][rV0/rV1]
        sm[OFF_V + bV * T + rV0] = sum2(accV0) + V_b[rV0];
        sm[OFF_V + bV * T + rV1] = sum2(accV1) + V_b[rV1];
    }
    __syncthreads();

    // ---- s[b] / d[b]: 32 tasks over 16 warps (2 each), product + warp reduce ----
    {
        const int warp = t >> 5;
        #pragma unroll
        for (int k2 = 0; k2 < 2; k2++) {
            const int task = warp + k2 * 16;
            const int pr = task >> 4, bb = task & 15;    // pr 0: s (wk*wq), 1: d (wv*wo)
            const float* ya = sm + OFF_Y + bb * 512 + pr * 256;
            float p = 0.f;
            #pragma unroll
            for (int k = 0; k < 4; k++) {
                int e = lane + k * 32;
                p += ya[e] * ya[128 + e];
            }
            #pragma unroll
            for (int off = 16; off > 0; off >>= 1)
                p += __shfl_xor_sync(0xffffffffu, p, off);
            if (lane == 0) sm[(pr ? OFF_D : OFF_S) + bb] = p;
        }
    }
    __syncthreads();

    // ---- epilogue (packed f32x2): 2 (b,q) per thread, interleaved for MUFU ILP ----
    {
        const int q  = t & 63;
        const int ba = t >> 6;        // 0..7
        const int bb = ba + 8;        // 8..15
        const float inv = 0.08838834764831843f * 1.4426950408889634f;  // log2e/sqrt(128)
        const float* xra = sm + OFF_X + ba * T;
        const float* xrb = sm + OFF_X + bb * T;
        const ulonglong2* xa2 = (const ulonglong2*)xra;
        const ulonglong2* xb2 = (const ulonglong2*)xrb;

        float aA = xra[q] * (sm[OFF_S + ba] * inv);
        float aB = xrb[q] * (sm[OFF_S + bb] * inv);
        float mA = fmaxf(aA * sm[OFF_MX + ba], aA * sm[OFF_MN + ba]);
        float mB = fmaxf(aB * sm[OFF_MX + bb], aB * sm[OFF_MN + bb]);
        ull aAd = pack2f(aA, aA), nmAd = pack2f(-mA, -mA);
        ull aBd = pack2f(aB, aB), nmBd = pack2f(-mB, -mB);
        ull sA = 0ull, wA = 0ull, sB = 0ull, wB = 0ull;

        #pragma unroll 4
        for (int j = 0; j < 16; j++) {
            ulonglong2 xpa = xa2[j];
            ulonglong2 xpb = xb2[j];
            {
                ull arg = ffma2(aAd, xpa.x, nmAd);
                float lo, hi; unpack2(arg, lo, hi);
                ull ep = pack2f(ex2f(lo), ex2f(hi));
                sA = add2(sA, ep); wA = ffma2(ep, xpa.x, wA);
                arg = ffma2(aAd, xpa.y, nmAd);
                unpack2(arg, lo, hi);
                ep = pack2f(ex2f(lo), ex2f(hi));
                sA = add2(sA, ep); wA = ffma2(ep, xpa.y, wA);
            }
            {
                ull arg = ffma2(aBd, xpb.x, nmBd);
                float lo, hi; unpack2(arg, lo, hi);
                ull ep = pack2f(ex2f(lo), ex2f(hi));
                sB = add2(sB, ep); wB = ffma2(ep, xpb.x, wB);
                arg = ffma2(aBd, xpb.y, nmBd);
                unpack2(arg, lo, hi);
                ep = pack2f(ex2f(lo), ex2f(hi));
                sB = add2(sB, ep); wB = ffma2(ep, xpb.y, wB);
            }
        }

        float mqa = __fdividef(sum2(wA), sum2(sA));
        float mqb = __fdividef(sum2(wB), sum2(sB));
        float ra = fmaf(mqa, sm[OFF_D + ba], sm[OFF_V + ba * T + q]);
        float rb = fmaf(mqb, sm[OFF_D + bb], sm[OFF_V + bb * T + q]);
        out[(size_t)(b0 + ba) * T + q] = ra > 0.f ? ra : expm1f(ra);
        out[(size_t)(b0 + bb) * T + q] = rb > 0.f ? rb : expm1f(rb);
    }
}

extern "C" void kernel_launch(void* const* d_in, const int* in_sizes, int n_in,
                              void* d_out, int out_size) {
    const float* x     = (const float*)d_in[0];
    const float* state = (const float*)d_in[1];
    const float* wk_w  = (const float*)d_in[2];
    const float* wk_b  = (const float*)d_in[3];
    const float* wq_w  = (const float*)d_in[4];
    const float* wq_b  = (const float*)d_in[5];
    const float* wv_w  = (const float*)d_in[6];
    const float* wv_b  = (const float*)d_in[7];
    const float* wo_w  = (const float*)d_in[8];
    const float* wo_b  = (const float*)d_in[9];
    const float* V_w   = (const float*)d_in[10];
    const float* V_b   = (const float*)d_in[11];

    static int configured = 0;
    if (!configured) {
        cudaFuncSetAttribute(fused_hyper_attn,
                             cudaFuncAttributeMaxDynamicSharedMemorySize,
                             SMEM_F * 4);
        configured = 1;
    }

    int nb   = in_sizes[0] / T;        // 4096 batches
    int grid = nb / B_TILE;            // 256 blocks
    fused_hyper_attn<<<grid, NTHREADS, SMEM_F * 4>>>(x, state,
                                                     wk_w, wk_b, wq_w, wq_b,
                                                     wv_w, wv_b, wo_w, wo_b,
                                                     V_w, V_b, (float*)d_out);
}

// round 10
// speedup vs baseline: 1.2474x; 1.2474x over previous
#include <cuda_runtime.h>
#include <cstdint>

typedef unsigned long long ull;

#define B_TILE   14           // batches per block (grid 293 ~= 2 blocks per SM, balanced)
#define B_PAD    16           // padded batch count for smem regions
#define NTHREADS 256
#define T        64
#define D        128
#define CTILE    16           // columns per weight tile (floats)
#define NTILES   8            // 128 / 16
#define RSTRIDE  20           // padded tile row stride in floats (5 float4, conflict-free)
#define NROWS    576          // wk(128)+wq(128)+wv(128)+wo(128)+V(64)
#define TILE_F   (NROWS * RSTRIDE)   // 11520 floats per buffer

// dynamic smem layout (float offsets)
#define OFF_WS    0
#define OFF_STATE (2 * TILE_F)            // 23040
#define OFF_X     (OFF_STATE + B_PAD*D)   // 25088
#define OFF_V     (OFF_X + B_PAD*T)       // 26112
#define OFF_S     (OFF_V + B_PAD*T)       // 27136
#define OFF_D     (OFF_S + B_PAD)
#define OFF_MN    (OFF_D + B_PAD)
#define OFF_MX    (OFF_MN + B_PAD)
#define SMEM_F    (OFF_MX + B_PAD)        // 27200 floats = 108800 B

__device__ __forceinline__ ull ffma2(ull a, ull b, ull c) {
    ull r;
    asm("fma.rn.f32x2 %0, %1, %2, %3;" : "=l"(r) : "l"(a), "l"(b), "l"(c));
    return r;
}
__device__ __forceinline__ float sum2(ull a) {
    float lo, hi;
    asm("mov.b64 {%0, %1}, %2;" : "=f"(lo), "=f"(hi) : "l"(a));
    return lo + hi;
}
__device__ __forceinline__ float ex2f(float x) {
    float r; asm("ex2.approx.ftz.f32 %0, %1;" : "=f"(r) : "f"(x)); return r;
}
__device__ __forceinline__ void cp16(unsigned int dst, const void* src) {
    asm volatile("cp.async.ca.shared.global [%0], [%1], 16;" :: "r"(dst), "l"(src));
}
__device__ __forceinline__ void cp_commit() {
    asm volatile("cp.async.commit_group;" ::: "memory");
}
template<int N> __device__ __forceinline__ void cp_wait() {
    asm volatile("cp.async.wait_group %0;" :: "n"(N) : "memory");
}

__global__ void __launch_bounds__(NTHREADS, 2)
fused_hyper_attn(const float* __restrict__ x, const float* __restrict__ state,
                 const float* __restrict__ wk_w, const float* __restrict__ wk_b,
                 const float* __restrict__ wq_w, const float* __restrict__ wq_b,
                 const float* __restrict__ wv_w, const float* __restrict__ wv_b,
                 const float* __restrict__ wo_w, const float* __restrict__ wo_b,
                 const float* __restrict__ V_w,  const float* __restrict__ V_b,
                 float* __restrict__ out, int nb)
{
    extern __shared__ __align__(16) float sm[];
    const int t  = threadIdx.x;
    const int b0 = blockIdx.x * B_TILE;
    const int valid = min(B_TILE, nb - b0);       // 14, or 8 on the last block
    const unsigned int sm_u32 = (unsigned int)__cvta_generic_to_shared(sm);

    // ---- stage weight tiles (cp.async, double buffered) ----
    #define STAGE(TI)                                                          \
    do {                                                                       \
        const int c0_ = (TI) * CTILE;                                          \
        const unsigned int wb_ = sm_u32 + (OFF_WS + ((TI) & 1) * TILE_F) * 4;  \
        _Pragma("unroll")                                                      \
        for (int i_ = 0; i_ < 9; i_++) {                                       \
            int q_ = t + i_ * 256;                                             \
            int row_ = q_ >> 2, cq_ = q_ & 3;                                  \
            const float* src_;                                                 \
            if      (i_ < 2) src_ = wk_w + (size_t)row_ * D;                   \
            else if (i_ < 4) src_ = wq_w + (size_t)(row_ - 128) * D;           \
            else if (i_ < 6) src_ = wv_w + (size_t)(row_ - 256) * D;           \
            else if (i_ < 8) src_ = wo_w + (size_t)(row_ - 384) * D;           \
            else             src_ = V_w  + (size_t)(row_ - 512) * D;           \
            cp16(wb_ + (unsigned int)(row_ * RSTRIDE + cq_ * 4) * 4,           \
                 src_ + c0_ + cq_ * 4);                                        \
        }                                                                      \
        cp_commit();                                                           \
    } while (0)

    STAGE(0);
    STAGE(1);

    // ---- stage state (valid x 128, zero-padded to 16) and x likewise ----
    {
        const float4 z4 = make_float4(0.f, 0.f, 0.f, 0.f);
        const float4* gs = (const float4*)(state + (size_t)b0 * D);
        const int vs4 = valid * 32;                   // valid float4s of state
        ((float4*)(sm + OFF_STATE))[t]       = (t       < vs4) ? gs[t]       : z4;
        ((float4*)(sm + OFF_STATE))[t + 256] = (t + 256 < vs4) ? gs[t + 256] : z4;
        const float4* gx = (const float4*)(x + (size_t)b0 * T);
        ((float4*)(sm + OFF_X))[t] = (t < valid * 16) ? gx[t] : z4;
    }
    if (t < B_PAD) { sm[OFF_S + t] = 0.f; sm[OFF_D + t] = 0.f; }
    __syncthreads();   // state/x visible

    // ---- per-batch min/max of x (16 threads, overlapped with tile waits) ----
    if (t < B_PAD) {
        const float* xr = sm + OFF_X + t * T;
        float mn = xr[0], mx = mn;
        #pragma unroll
        for (int k = 1; k < T; k++) {
            float v = xr[k];
            mn = fminf(mn, v); mx = fmaxf(mx, v);
        }
        sm[OFF_MN + t] = mn; sm[OFF_MX + t] = mx;
    }

    // ---- row ownership ----
    const int g    = t >> 7;               // 0: K/Q   1: V/O
    const int e    = t & 127;
    const int rowA = g * 256 + e;          // wk or wv
    const int rowB = g * 256 + 128 + e;    // wq or wo
    const int rV   = t & 63;               // V_w row
    const int rowV = 512 + rV;
    const int bg   = t >> 6;               // 0..3 (uniform per warp)
    const float bAv = (g ? wv_b : wk_b)[e];
    const float bBv = (g ? wo_b : wq_b)[e];
    const float vBv = V_b[rV];

    ull accA[B_TILE], accB[B_TILE], accV[4];
    #pragma unroll
    for (int b = 0; b < B_TILE; b++) { accA[b] = 0ull; accB[b] = 0ull; }
    #pragma unroll
    for (int i = 0; i < 4; i++) accV[i] = 0ull;

    const ulonglong2* st = (const ulonglong2*)(sm + OFF_STATE);  // [16][32] 16B units

    // ---- pipelined main loop over 8 column tiles ----
    for (int ti = 0; ti < NTILES; ti++) {
        if (ti < NTILES - 1) cp_wait<1>(); else cp_wait<0>();
        __syncthreads();                       // tile ti visible to all

        const ulonglong2* wt = (const ulonglong2*)(sm + OFF_WS + (ti & 1) * TILE_F);
        const int jb = ti * 4;                 // float4-column base within state row
        #pragma unroll
        for (int j = 0; j < 4; j++) {
            ulonglong2 va = wt[rowA * 5 + j];
            ulonglong2 vb = wt[rowB * 5 + j];
            ulonglong2 vv = wt[rowV * 5 + j];
            #pragma unroll
            for (int b = 0; b < B_TILE; b++) {
                ulonglong2 s = st[b * 32 + jb + j];
                accA[b] = ffma2(s.x, va.x, accA[b]);
                accA[b] = ffma2(s.y, va.y, accA[b]);
                accB[b] = ffma2(s.x, vb.x, accB[b]);
                accB[b] = ffma2(s.y, vb.y, accB[b]);
            }
            #pragma unroll
            for (int i = 0; i < 4; i++) {
                ulonglong2 s = st[(bg * 4 + i) * 32 + jb + j];
                accV[i] = ffma2(s.x, vv.x, accV[i]);
                accV[i] = ffma2(s.y, vv.y, accV[i]);
            }
        }

        __syncthreads();                       // all done reading buf[ti&1]
        if (ti + 2 < NTILES) STAGE(ti + 2);
    }

    // ---- finalize s[b] / d[b]: p = |yA|*|yB|, warp-reduce, atomic into smem ----
    {
        float p[B_TILE];
        #pragma unroll
        for (int b = 0; b < B_TILE; b++)
            p[b] = fabsf(sum2(accA[b]) + bAv) * fabsf(sum2(accB[b]) + bBv);
        #pragma unroll
        for (int b = 0; b < B_TILE; b++) {
            #pragma unroll
            for (int off = 16; off > 0; off >>= 1)
                p[b] += __shfl_xor_sync(0xffffffffu, p[b], off);
        }
        if ((t & 31) == 0) {
            float* dst = sm + (g ? OFF_D : OFF_S);
            #pragma unroll
            for (int b = 0; b < B_TILE; b++) atomicAdd(&dst[b], p[b]);
        }
    }

    // ---- finalize v[b][r] (guard batches >= B_TILE) ----
    #pragma unroll
    for (int i = 0; i < 4; i++) {
        int b = bg * 4 + i;
        if (b < B_TILE) sm[OFF_V + b * T + rV] = sum2(accV[i]) + vBv;
    }

    __syncthreads();

    // ---- epilogue: per (b,q) softmax over k of c*x_q*x_k (log2 domain), then elu
    {
        const float inv = 0.08838834764831843f * 1.4426950408889634f;  // log2e/sqrt(128)
        #pragma unroll
        for (int i = 0; i < 4; i++) {
            const int idx = t + i * 256;           // 0 .. 1023 ; tasks < 896
            if (idx >= B_TILE * T) break;
            const int b = idx >> 6, q = idx & 63;
            const float* xr = sm + OFF_X + b * T;
            const float4* xr4 = (const float4*)xr;
            float a2 = xr[q] * (sm[OFF_S + b] * inv);
            float m2 = fmaxf(a2 * sm[OFF_MX + b], a2 * sm[OFF_MN + b]);
            float sum = 0.f, ws = 0.f;
            #pragma unroll 4
            for (int j = 0; j < 16; j++) {
                float4 xv = xr4[j];
                float e0 = ex2f(fmaf(a2, xv.x, -m2)); sum += e0; ws = fmaf(e0, xv.x, ws);
                float e1 = ex2f(fmaf(a2, xv.y, -m2)); sum += e1; ws = fmaf(e1, xv.y, ws);
                float e2 = ex2f(fmaf(a2, xv.z, -m2)); sum += e2; ws = fmaf(e2, xv.z, ws);
                float e3 = ex2f(fmaf(a2, xv.w, -m2)); sum += e3; ws = fmaf(e3, xv.w, ws);
            }
            float m = __fdividef(ws, sum);
            float r = fmaf(m, sm[OFF_D + b], sm[OFF_V + b * T + q]);
            if (b < valid)
                out[(size_t)(b0 + b) * T + q] = r > 0.f ? r : expm1f(r);
        }
    }
}

extern "C" void kernel_launch(void* const* d_in, const int* in_sizes, int n_in,
                              void* d_out, int out_size) {
    const float* x     = (const float*)d_in[0];
    const float* state = (const float*)d_in[1];
    const float* wk_w  = (const float*)d_in[2];
    const float* wk_b  = (const float*)d_in[3];
    const float* wq_w  = (const float*)d_in[4];
    const float* wq_b  = (const float*)d_in[5];
    const float* wv_w  = (const float*)d_in[6];
    const float* wv_b  = (const float*)d_in[7];
    const float* wo_w  = (const float*)d_in[8];
    const float* wo_b  = (const float*)d_in[9];
    const float* V_w   = (const float*)d_in[10];
    const float* V_b   = (const float*)d_in[11];

    static int configured = 0;
    if (!configured) {
        cudaFuncSetAttribute(fused_hyper_attn,
                             cudaFuncAttributeMaxDynamicSharedMemorySize,
                             SMEM_F * 4);
        configured = 1;
    }

    int nb   = in_sizes[0] / T;                 // 4096 batches
    int grid = (nb + B_TILE - 1) / B_TILE;      // 293 blocks
    fused_hyper_attn<<<grid, NTHREADS, SMEM_F * 4>>>(x, state,
                                                     wk_w, wk_b, wq_w, wq_b,
                                                     wv_w, wv_b, wo_w, wo_b,
                                                     V_w, V_b, (float*)d_out, nb);
}